// round 2
// baseline (speedup 1.0000x reference)
#include <cuda_runtime.h>

// Chen's relation signature combine.
// DIM=8, DEPTH=4 -> flat = 8 + 64 + 512 + 4096 = 4680 floats per row.
// Level offsets: L1 @ 0 (8), L2 @ 8 (64), L3 @ 72 (512), L4 @ 584 (4096).
//
// out_L1    = a1 + b1
// out_L2[t] = a2[t] + b2[t] + a1[t/8]*b1[t%8]
// out_L3[t] = a3[t] + b3[t] + a1[t/64]*b2[t%64] + a2[t/8]*b1[t%8]
// out_L4[t] = a4[t] + b4[t] + a1[t/512]*b3[t%512] + a2[t/64]*b2[t%64] + a3[t/8]*b1[t%8]
//
// All cross-term operands live in the first 584 floats (levels 1..3) of each
// input row -> stage only those prefixes in shared memory (2 * 2336 B / CTA).
// Additive terms stream straight from global as float4.

#define FLAT 4680
#define NV4  1170    // FLAT / 4
#define PREF 584     // 8 + 64 + 512
#define NPV4 146     // PREF / 4
#define NTHREADS 256

__global__ __launch_bounds__(NTHREADS)
void sig_combine_kernel(const float* __restrict__ g1,
                        const float* __restrict__ g2,
                        float* __restrict__ gout)
{
    __shared__ float a[PREF];
    __shared__ float b[PREF];

    const int row = blockIdx.x;
    const int tid = threadIdx.x;

    const float4* g1v = reinterpret_cast<const float4*>(g1 + (size_t)row * FLAT);
    const float4* g2v = reinterpret_cast<const float4*>(g2 + (size_t)row * FLAT);

    // Stage prefixes (levels 1..3) into shared.
    if (tid < NPV4) {
        reinterpret_cast<float4*>(a)[tid] = g1v[tid];
        reinterpret_cast<float4*>(b)[tid] = g2v[tid];
    }
    __syncthreads();

    float4* outv = reinterpret_cast<float4*>(gout + (size_t)row * FLAT);

    for (int v = tid; v < NV4; v += NTHREADS) {
        const int base = v * 4;
        float4 va = g1v[v];
        float4 vb = g2v[v];
        float4 r;
        float* rp = &r.x;
        const float* ap = &va.x;
        const float* bp = &vb.x;

        if (base >= 584) {
            // Level 4 (bulk of work): t in [0, 4096)
            #pragma unroll
            for (int e = 0; e < 4; e++) {
                int t = base + e - 584;
                float val = ap[e] + bp[e];
                val += a[t >> 9] * b[72 + (t & 511)];
                val += a[8 + (t >> 6)] * b[8 + (t & 63)];
                val += a[72 + (t >> 3)] * b[t & 7];
                rp[e] = val;
            }
        } else if (base >= 72) {
            // Level 3
            #pragma unroll
            for (int e = 0; e < 4; e++) {
                int t = base + e - 72;
                float val = ap[e] + bp[e];
                val += a[t >> 6] * b[8 + (t & 63)];
                val += a[8 + (t >> 3)] * b[t & 7];
                rp[e] = val;
            }
        } else if (base >= 8) {
            // Level 2
            #pragma unroll
            for (int e = 0; e < 4; e++) {
                int t = base + e - 8;
                rp[e] = ap[e] + bp[e] + a[t >> 3] * b[t & 7];
            }
        } else {
            // Level 1
            #pragma unroll
            for (int e = 0; e < 4; e++) {
                rp[e] = ap[e] + bp[e];
            }
        }
        outv[v] = r;
    }
}

extern "C" void kernel_launch(void* const* d_in, const int* in_sizes, int n_in,
                              void* d_out, int out_size)
{
    const float* s1 = (const float*)d_in[0];
    const float* s2 = (const float*)d_in[1];
    float* out = (float*)d_out;

    const int B = in_sizes[0] / FLAT;   // 16384
    sig_combine_kernel<<<B, NTHREADS>>>(s1, s2, out);
}